// round 12
// baseline (speedup 1.0000x reference)
#include <cuda_runtime.h>

// SpikingAttentionJAX — ONE kernel, ZERO grid sync, warp0-only finalizer.
// LIF scan collapses to per-token occurrence counts (per-entry updates
// commute; entry t's final state depends only on count n_t and v0[t]).
//
// 125 blocks x 1024 threads; block b owns vocab slice [1024b, 1024b+1024).
// Each block histograms the whole 8192-token stream (8 tokens/thread, two
// independent int4 loads, L2-broadcast) into shared memory; v0 prefetched
// before the scan. Then LIF replay, gain store (0.6 spiked / 1.0), REDUX
// warp top-5 -> warp0 merges 160 candidates -> block top-5 -> g_cand
// (all 5 stores by lane 0). Done-counter: lane 0 fences + increments; the
// last-flag is broadcast by ONE warp shuffle (no block barrier); warps 1-31
// retire immediately after candidate deposit. The last-arriving block's
// warp 0 alone merges 625 candidates (20 keys/lane register insertion +
// 5 REDUX rounds) and writes the 5 winners (1.5). JAX top_k tie-break
// (lower index wins) via packed monotone key (ordered_float(v)<<32 | ~idx).

static constexpr float DECAY     = 0.7f;
static constexpr float THETA     = 1.0f;
static constexpr float GAIN_UP   = 1.5f;
static constexpr float GAIN_DOWN = 0.6f;
static constexpr int   KW   = 5;
static constexpr int   NT   = 1024;
static constexpr int   NW   = NT / 32;       // 32 warps
static constexpr int   MAXB = 256;           // >= grid (125)

__device__ unsigned long long g_cand[MAXB * KW];
__device__ unsigned g_done = 0;              // monotonic across graph replays

__device__ __forceinline__ unsigned ordered_bits(float f) {
    unsigned u = __float_as_uint(f);
    return (u & 0x80000000u) ? ~u : (u | 0x80000000u);   // >0 for finite f
}

__global__ __launch_bounds__(NT)
void k_main(const int* __restrict__ tok, const float* __restrict__ v0,
            float* __restrict__ out, int seq, int vocab, int nblocks) {
    const int tid  = threadIdx.x;
    const int lane = tid & 31;
    const int wid  = tid >> 5;
    const int base = blockIdx.x * NT;            // this block's vocab slice
    const int i    = base + tid;                 // this thread's vocab entry
    const bool live = (i < vocab);

    __shared__ int      sh_cnt[NT];
    __shared__ unsigned s_val[NW * KW];          // 160 block candidates
    __shared__ unsigned s_idx[NW * KW];

    // ---- prefetch v0 early (independent of histogram; hides DRAM latency) ----
    float vpre = live ? __ldg(&v0[i]) : 0.0f;

    sh_cnt[tid] = 0;
    __syncthreads();

    // ---- histogram whole token stream for this slice (2 indep int4/thread) ----
    const int4* tok4 = reinterpret_cast<const int4*>(tok);
    const int   n4   = seq >> 2;                 // 2048
    int4 ta, tb;
    const bool hasA = (tid < n4), hasB = (tid + NT < n4);
    if (hasA) ta = __ldg(&tok4[tid]);
    if (hasB) tb = __ldg(&tok4[tid + NT]);
    if (hasA) {
        int t;
        t = ta.x; t = t < 0 ? 0 : (t >= vocab ? vocab - 1 : t);
        if ((unsigned)(t - base) < (unsigned)NT) atomicAdd(&sh_cnt[t - base], 1);
        t = ta.y; t = t < 0 ? 0 : (t >= vocab ? vocab - 1 : t);
        if ((unsigned)(t - base) < (unsigned)NT) atomicAdd(&sh_cnt[t - base], 1);
        t = ta.z; t = t < 0 ? 0 : (t >= vocab ? vocab - 1 : t);
        if ((unsigned)(t - base) < (unsigned)NT) atomicAdd(&sh_cnt[t - base], 1);
        t = ta.w; t = t < 0 ? 0 : (t >= vocab ? vocab - 1 : t);
        if ((unsigned)(t - base) < (unsigned)NT) atomicAdd(&sh_cnt[t - base], 1);
    }
    if (hasB) {
        int t;
        t = tb.x; t = t < 0 ? 0 : (t >= vocab ? vocab - 1 : t);
        if ((unsigned)(t - base) < (unsigned)NT) atomicAdd(&sh_cnt[t - base], 1);
        t = tb.y; t = t < 0 ? 0 : (t >= vocab ? vocab - 1 : t);
        if ((unsigned)(t - base) < (unsigned)NT) atomicAdd(&sh_cnt[t - base], 1);
        t = tb.z; t = t < 0 ? 0 : (t >= vocab ? vocab - 1 : t);
        if ((unsigned)(t - base) < (unsigned)NT) atomicAdd(&sh_cnt[t - base], 1);
        t = tb.w; t = t < 0 ? 0 : (t >= vocab ? vocab - 1 : t);
        if ((unsigned)(t - base) < (unsigned)NT) atomicAdd(&sh_cnt[t - base], 1);
    }
    // generic tails (inactive for seq=8192, NT=1024)
    for (int c = (n4 > 2 * NT ? 2 * NT : n4) + tid; c < n4; c += NT) {
        int4 t4 = __ldg(&tok4[c]);
        int t;
        t = t4.x; t = t < 0 ? 0 : (t >= vocab ? vocab - 1 : t);
        if ((unsigned)(t - base) < (unsigned)NT) atomicAdd(&sh_cnt[t - base], 1);
        t = t4.y; t = t < 0 ? 0 : (t >= vocab ? vocab - 1 : t);
        if ((unsigned)(t - base) < (unsigned)NT) atomicAdd(&sh_cnt[t - base], 1);
        t = t4.z; t = t < 0 ? 0 : (t >= vocab ? vocab - 1 : t);
        if ((unsigned)(t - base) < (unsigned)NT) atomicAdd(&sh_cnt[t - base], 1);
        t = t4.w; t = t < 0 ? 0 : (t >= vocab ? vocab - 1 : t);
        if ((unsigned)(t - base) < (unsigned)NT) atomicAdd(&sh_cnt[t - base], 1);
    }
    for (int c = (n4 << 2) + tid; c < seq; c += NT) {
        int t = __ldg(&tok[c]);
        t = t < 0 ? 0 : (t >= vocab ? vocab - 1 : t);
        if ((unsigned)(t - base) < (unsigned)NT) atomicAdd(&sh_cnt[t - base], 1);
    }
    __syncthreads();

    // ---- LIF replay + gains ----
    unsigned uval = 0u;                          // 0 = invalid/popped sentinel
    unsigned idx  = (unsigned)i;
    if (live) {
        int   cnt = sh_cnt[tid];
        float v   = vpre;
        int s = 0;
        for (int it = 0; it < cnt; it++) {
            float vn = DECAY * v + 1.0f;
            if (vn >= THETA) { v = vn - THETA; s++; }
            else             { v = vn; }
        }
        out[i] = (s > 0) ? GAIN_DOWN : 1.0f;
        uval = ordered_bits(v);
    }

    // ---- warp top-5: REDUX.UMAX(value) + REDUX.UMIN(index) per round ----
    #pragma unroll
    for (int r = 0; r < KW; r++) {
        unsigned m    = __reduce_max_sync(0xffffffffu, uval);
        unsigned cand = (uval == m) ? idx : 0xffffffffu;
        unsigned wi   = __reduce_min_sync(0xffffffffu, cand);
        if (lane == 0) { s_val[wid * KW + r] = m; s_idx[wid * KW + r] = wi; }
        if (uval == m && idx == wi) uval = 0u;
    }
    __syncthreads();                             // candidates visible to warp 0
    if (wid != 0) return;                        // warps 1-31 retire now

    // ---- warp 0: merge 160 (val,idx) -> block top-5 -> g_cand (lane 0) ----
    {
        unsigned av[KW], ai[KW];                 // 5 slots per lane, static idx
        #pragma unroll
        for (int s = 0; s < KW; s++) {
            av[s] = s_val[s * 32 + lane];
            ai[s] = s_idx[s * 32 + lane];
        }
        #pragma unroll
        for (int r = 0; r < KW; r++) {
            unsigned bv = av[0], bi = ai[0];
            #pragma unroll
            for (int s = 1; s < KW; s++) {
                bool better = (av[s] > bv) || (av[s] == bv && ai[s] < bi);
                if (better) { bv = av[s]; bi = ai[s]; }
            }
            unsigned m    = __reduce_max_sync(0xffffffffu, bv);
            unsigned cand = (bv == m) ? bi : 0xffffffffu;
            unsigned wi   = __reduce_min_sync(0xffffffffu, cand);
            if (lane == 0)
                g_cand[blockIdx.x * KW + r] =
                    ((unsigned long long)m << 32) |
                    (unsigned long long)(0xffffffffu - wi);
            #pragma unroll
            for (int s = 0; s < KW; s++)
                if (av[s] == m && ai[s] == wi) { av[s] = 0u; ai[s] = 0xffffffffu; }
        }
    }

    // ---- done-counter, warp-scope broadcast (no block barrier) ----
    unsigned last = 0u;
    if (lane == 0) {
        __threadfence();                         // release: out[] (via BAR-observed
                                                 // CTA order) + lane0's g_cand stores
        unsigned old = atomicAdd(&g_done, 1);
        last = (((old + 1) % (unsigned)nblocks) == 0u) ? 1u : 0u;
    }
    last = __shfl_sync(0xffffffffu, last, 0);
    if (!last) return;
    __threadfence();                             // acquire all blocks' g_cand

    // ---- finalizer: warp 0 only. 625 keys, 20/lane, register top-5 ----
    const int ncand = nblocks * KW;              // 625
    unsigned long long t0 = 0, t1 = 0, t2 = 0, t3 = 0, t4 = 0;  // sorted desc
    #pragma unroll
    for (int j = 0; j < 20; j++) {               // 32*20 = 640 >= 625
        int c = lane + (j << 5);
        unsigned long long k = (c < ncand) ? __ldcg(&g_cand[c]) : 0ull;
        if (k > t4) {
            if      (k > t0) { t4 = t3; t3 = t2; t2 = t1; t1 = t0; t0 = k; }
            else if (k > t1) { t4 = t3; t3 = t2; t2 = t1; t1 = k; }
            else if (k > t2) { t4 = t3; t3 = t2; t2 = k; }
            else if (k > t3) { t4 = t3; t3 = k; }
            else             { t4 = k; }
        }
    }
    #pragma unroll
    for (int r = 0; r < KW; r++) {
        unsigned hv = (unsigned)(t0 >> 32);
        unsigned wm = __reduce_max_sync(0xffffffffu, hv);
        unsigned lo = (hv == wm) ? (unsigned)(t0 & 0xffffffffull) : 0u;
        unsigned wl = __reduce_max_sync(0xffffffffu, lo);  // max ~idx = min idx
        if (lane == 0)
            out[0xffffffffu - wl] = GAIN_UP;     // >=5 unique real keys exist
        unsigned long long win = ((unsigned long long)wm << 32) | wl;
        if (t0 == win) { t0 = t1; t1 = t2; t2 = t3; t3 = t4; t4 = 0ull; }
    }
}

// ---------------------------------------------------------------- launch
extern "C" void kernel_launch(void* const* d_in, const int* in_sizes, int n_in,
                              void* d_out, int out_size) {
    const int*   tok = (const int*)d_in[0];
    const float* v0  = (const float*)d_in[1];
    const int seq   = in_sizes[0];
    const int vocab = in_sizes[1];
    float* out = (float*)d_out;

    int gblocks = (vocab + NT - 1) / NT;         // 125 for vocab=128000
    k_main<<<gblocks, NT>>>(tok, v0, out, seq, vocab, gblocks);
}

// round 13
// speedup vs baseline: 1.7343x; 1.7343x over previous
#include <cuda_runtime.h>

// SpikingAttentionJAX — ONE kernel, ZERO grid sync (R10 structure, packed keys).
// LIF scan collapses to per-token occurrence counts (per-entry updates
// commute; entry t's final state depends only on count n_t and v0[t]).
//
// 125 blocks x 1024 threads; block b owns vocab slice [1024b, 1024b+1024).
// Each block histograms the whole 8192-token stream (8 tokens/thread, two
// independent int4 loads, L2-broadcast) into shared memory; v0 prefetched
// before the scan to hide its DRAM latency. Then LIF replay, gain store
// (0.6 spiked / 1.0), REDUX warp top-5 (packed 64-bit keys in smem),
// warp0 merges 160 packed keys -> block top-5 -> g_cand; done-counter:
// LAST arriving block finalizes: 625 keys, 1 key/thread, per-warp REDUX
// top-5 (sync-free), ONE barrier, warp0 register merge, 5 winner stores
// (1.5). JAX top_k tie-break (lower index wins) via monotone packed key
// (ordered_float(v) << 32) | ~index  — strictly larger = better, unique.

static constexpr float DECAY     = 0.7f;
static constexpr float THETA     = 1.0f;
static constexpr float GAIN_UP   = 1.5f;
static constexpr float GAIN_DOWN = 0.6f;
static constexpr int   KW   = 5;
static constexpr int   NT   = 1024;
static constexpr int   NW   = NT / 32;       // 32 warps
static constexpr int   MAXB = 256;           // >= grid (125)

__device__ unsigned long long g_cand[MAXB * KW];
__device__ unsigned g_done = 0;              // monotonic across graph replays

__device__ __forceinline__ unsigned ordered_bits(float f) {
    unsigned u = __float_as_uint(f);
    return (u & 0x80000000u) ? ~u : (u | 0x80000000u);   // >0 for finite f
}

__global__ __launch_bounds__(NT)
void k_main(const int* __restrict__ tok, const float* __restrict__ v0,
            float* __restrict__ out, int seq, int vocab, int nblocks) {
    const int tid  = threadIdx.x;
    const int lane = tid & 31;
    const int wid  = tid >> 5;
    const int base = blockIdx.x * NT;            // this block's vocab slice
    const int i    = base + tid;                 // this thread's vocab entry
    const bool live = (i < vocab);

    __shared__ int                sh_cnt[NT];
    __shared__ unsigned long long s_m[NW * KW];  // 160 packed candidates
    __shared__ unsigned           s_last;

    // ---- prefetch v0 early (independent of histogram; hides DRAM latency) ----
    float vpre = live ? __ldg(&v0[i]) : 0.0f;

    sh_cnt[tid] = 0;
    __syncthreads();

    // ---- histogram whole token stream for this slice (2 indep int4/thread) ----
    const int4* tok4 = reinterpret_cast<const int4*>(tok);
    const int   n4   = seq >> 2;                 // 2048
    int4 ta, tb;
    const bool hasA = (tid < n4), hasB = (tid + NT < n4);
    if (hasA) ta = __ldg(&tok4[tid]);
    if (hasB) tb = __ldg(&tok4[tid + NT]);
    if (hasA) {
        int t;
        t = ta.x; t = t < 0 ? 0 : (t >= vocab ? vocab - 1 : t);
        if ((unsigned)(t - base) < (unsigned)NT) atomicAdd(&sh_cnt[t - base], 1);
        t = ta.y; t = t < 0 ? 0 : (t >= vocab ? vocab - 1 : t);
        if ((unsigned)(t - base) < (unsigned)NT) atomicAdd(&sh_cnt[t - base], 1);
        t = ta.z; t = t < 0 ? 0 : (t >= vocab ? vocab - 1 : t);
        if ((unsigned)(t - base) < (unsigned)NT) atomicAdd(&sh_cnt[t - base], 1);
        t = ta.w; t = t < 0 ? 0 : (t >= vocab ? vocab - 1 : t);
        if ((unsigned)(t - base) < (unsigned)NT) atomicAdd(&sh_cnt[t - base], 1);
    }
    if (hasB) {
        int t;
        t = tb.x; t = t < 0 ? 0 : (t >= vocab ? vocab - 1 : t);
        if ((unsigned)(t - base) < (unsigned)NT) atomicAdd(&sh_cnt[t - base], 1);
        t = tb.y; t = t < 0 ? 0 : (t >= vocab ? vocab - 1 : t);
        if ((unsigned)(t - base) < (unsigned)NT) atomicAdd(&sh_cnt[t - base], 1);
        t = tb.z; t = t < 0 ? 0 : (t >= vocab ? vocab - 1 : t);
        if ((unsigned)(t - base) < (unsigned)NT) atomicAdd(&sh_cnt[t - base], 1);
        t = tb.w; t = t < 0 ? 0 : (t >= vocab ? vocab - 1 : t);
        if ((unsigned)(t - base) < (unsigned)NT) atomicAdd(&sh_cnt[t - base], 1);
    }
    // tail for seq not a multiple of 4*NT elements handled generically:
    for (int c = 2 * NT + tid; c < n4; c += NT) {
        int4 t4 = __ldg(&tok4[c]);
        int t;
        t = t4.x; t = t < 0 ? 0 : (t >= vocab ? vocab - 1 : t);
        if ((unsigned)(t - base) < (unsigned)NT) atomicAdd(&sh_cnt[t - base], 1);
        t = t4.y; t = t < 0 ? 0 : (t >= vocab ? vocab - 1 : t);
        if ((unsigned)(t - base) < (unsigned)NT) atomicAdd(&sh_cnt[t - base], 1);
        t = t4.z; t = t < 0 ? 0 : (t >= vocab ? vocab - 1 : t);
        if ((unsigned)(t - base) < (unsigned)NT) atomicAdd(&sh_cnt[t - base], 1);
        t = t4.w; t = t < 0 ? 0 : (t >= vocab ? vocab - 1 : t);
        if ((unsigned)(t - base) < (unsigned)NT) atomicAdd(&sh_cnt[t - base], 1);
    }
    for (int c = (n4 << 2) + tid; c < seq; c += NT) {
        int t = __ldg(&tok[c]);
        t = t < 0 ? 0 : (t >= vocab ? vocab - 1 : t);
        if ((unsigned)(t - base) < (unsigned)NT) atomicAdd(&sh_cnt[t - base], 1);
    }
    __syncthreads();

    // ---- LIF replay + gains ----
    unsigned uval = 0u;                          // 0 = invalid/popped sentinel
    unsigned idx  = (unsigned)i;
    if (live) {
        int   cnt = sh_cnt[tid];
        float v   = vpre;
        int s = 0;
        for (int it = 0; it < cnt; it++) {
            float vn = DECAY * v + 1.0f;
            if (vn >= THETA) { v = vn - THETA; s++; }
            else             { v = vn; }
        }
        out[i] = (s > 0) ? GAIN_DOWN : 1.0f;
        uval = ordered_bits(v);
    }

    // ---- warp top-5: REDUX.UMAX(value) + REDUX.UMIN(index); packed STS.64 ----
    #pragma unroll
    for (int r = 0; r < KW; r++) {
        unsigned m    = __reduce_max_sync(0xffffffffu, uval);
        unsigned cand = (uval == m) ? idx : 0xffffffffu;
        unsigned wi   = __reduce_min_sync(0xffffffffu, cand);
        if (lane == 0)
            s_m[wid * KW + r] = ((unsigned long long)m << 32) |
                                (unsigned long long)(0xffffffffu - wi);
        if (uval == m && idx == wi) uval = 0u;
    }
    __syncthreads();

    // ---- warp 0: merge 160 packed keys -> block top-5 -> g_cand ----
    if (wid == 0) {
        unsigned long long a[KW];                // 5 packed slots/lane
        #pragma unroll
        for (int s = 0; s < KW; s++) a[s] = s_m[s * 32 + lane];
        #pragma unroll
        for (int r = 0; r < KW; r++) {
            unsigned long long b = a[0];
            #pragma unroll
            for (int s = 1; s < KW; s++) if (a[s] > b) b = a[s];   // monotone key
            unsigned bh = (unsigned)(b >> 32);
            unsigned wm = __reduce_max_sync(0xffffffffu, bh);
            unsigned bl = (bh == wm) ? (unsigned)(b & 0xffffffffull) : 0u;
            unsigned wl = __reduce_max_sync(0xffffffffu, bl);      // max ~idx
            unsigned long long win = ((unsigned long long)wm << 32) | wl;
            if (lane == 0) g_cand[blockIdx.x * KW + r] = win;
            #pragma unroll
            for (int s = 0; s < KW; s++) if (a[s] == win) a[s] = 0ull;
        }
    }

    // ---- done-counter: last-arriving block finalizes (no spinning) ----
    if (tid == 0) {
        __threadfence();                         // release out[] + g_cand
        unsigned old = atomicAdd(&g_done, 1);
        s_last = (((old + 1) % (unsigned)nblocks) == 0u) ? 1u : 0u;
    }
    __syncthreads();
    if (!s_last) return;
    __threadfence();                             // acquire all blocks' g_cand

    // ---- finalizer: 625 keys, 1/thread -> per-warp REDUX top-5 -> 1 BAR ----
    const int ncand = nblocks * KW;              // 625 <= 1024
    unsigned long long key = (tid < ncand) ? g_cand[tid] : 0ull;
    unsigned hv = (unsigned)(key >> 32);
    unsigned lo = (unsigned)(key & 0xffffffffull);

    #pragma unroll
    for (int r = 0; r < KW; r++) {
        unsigned wm = __reduce_max_sync(0xffffffffu, hv);
        unsigned cl = (hv == wm) ? lo : 0u;
        unsigned wl = __reduce_max_sync(0xffffffffu, cl);  // max ~idx = min idx
        if (lane == 0) s_m[wid * KW + r] = ((unsigned long long)wm << 32) | wl;
        if (hv == wm && lo == wl) { hv = 0u; lo = 0u; }    // pop (keys unique)
    }
    __syncthreads();                             // single barrier in finalize

    if (wid == 0) {
        unsigned long long a[KW];                // 5 slots/lane over 160 keys
        #pragma unroll
        for (int s = 0; s < KW; s++) a[s] = s_m[s * 32 + lane];
        #pragma unroll
        for (int r = 0; r < KW; r++) {
            unsigned long long b = a[0];
            #pragma unroll
            for (int s = 1; s < KW; s++) if (a[s] > b) b = a[s];
            unsigned bh = (unsigned)(b >> 32);
            unsigned wm = __reduce_max_sync(0xffffffffu, bh);
            unsigned bl = (bh == wm) ? (unsigned)(b & 0xffffffffull) : 0u;
            unsigned wl = __reduce_max_sync(0xffffffffu, bl);
            if (lane == 0 && wm != 0u)
                out[0xffffffffu - wl] = GAIN_UP; // >=5 unique real keys exist
            unsigned long long win = ((unsigned long long)wm << 32) | wl;
            #pragma unroll
            for (int s = 0; s < KW; s++) if (a[s] == win) a[s] = 0ull;
        }
    }
}

// ---------------------------------------------------------------- launch
extern "C" void kernel_launch(void* const* d_in, const int* in_sizes, int n_in,
                              void* d_out, int out_size) {
    const int*   tok = (const int*)d_in[0];
    const float* v0  = (const float*)d_in[1];
    const int seq   = in_sizes[0];
    const int vocab = in_sizes[1];
    float* out = (float*)d_out;

    int gblocks = (vocab + NT - 1) / NT;         // 125 for vocab=128000
    k_main<<<gblocks, NT>>>(tok, v0, out, seq, vocab, gblocks);
}